// round 12
// baseline (speedup 1.0000x reference)
#include <cuda_runtime.h>
#include <math.h>

#define B_SETS 65536
#define P      22
#define INF_   6
#define HID    64
#define OUTD   128

#define WPB     8
#define THREADS (WPB * 32)
#define GRID    444                 // 148 SMs * 3 blocks/SM
#define S       8
#define NCHUNKS (B_SETS / S)        // 8192
#define NWARPS  (GRID * WPB)        // 3552
#define BASEK   2                   // base chunks per warp
#define BASE_CHUNKS (NWARPS * BASEK)   // 7104 ; tail = 1088 = NWARPS*34/111

__device__ __forceinline__ unsigned long long pack2(float lo, float hi) {
    unsigned long long r;
    asm("mov.b64 %0, {%1,%2};" : "=l"(r) : "f"(lo), "f"(hi));
    return r;
}
__device__ __forceinline__ void unpack2(unsigned long long v, float& lo, float& hi) {
    asm("mov.b64 {%0,%1}, %2;" : "=f"(lo), "=f"(hi) : "l"(v));
}
__device__ __forceinline__ unsigned long long fma2(unsigned long long a,
                                                   unsigned long long b,
                                                   unsigned long long c) {
    unsigned long long d;
    asm("fma.rn.f32x2 %0, %1, %2, %3;" : "=l"(d) : "l"(a), "l"(b), "l"(c));
    return d;
}

// fast atan2: minimax deg-11 odd poly on [0,1], abs err ~1e-6 (output tol 1e-3)
__device__ __forceinline__ float fast_atan2(float y, float x) {
    const float ax = fabsf(x), ay = fabsf(y);
    const float mx = fmaxf(ax, ay), mn = fminf(ax, ay);
    float t = (mx > 0.f) ? __fdividef(mn, mx) : 0.f;
    const float a = t * t;
    float p = fmaf(a, -0.01172120f, 0.05265332f);
    p = fmaf(a, p, -0.11643287f);
    p = fmaf(a, p,  0.19354346f);
    p = fmaf(a, p, -0.33262347f);
    p = fmaf(a, p,  0.99997726f);
    float r = t * p;
    if (ay > ax)  r = 1.57079632679f - r;
    if (x < 0.f)  r = 3.14159265359f - r;
    return (y < 0.f) ? -r : r;
}

__global__ __launch_bounds__(THREADS, 3)
void set_encoder_kernel(const float* __restrict__ player_locs,
                        const float* __restrict__ actor_locs,
                        const float* __restrict__ flags,
                        const int*   __restrict__ mask,
                        const float* __restrict__ W1,
                        const float* __restrict__ b1,
                        const float* __restrict__ W2,
                        const float* __restrict__ b2,
                        float*       __restrict__ out)
{
    __shared__ float  sW2[HID * OUTD];            // 32 KB
    __shared__ float  shh[WPB][HID][S];           // pooled hidden, 8 sets: 32B/row
    __shared__ float4 sf0[WPB][P];                // dx,dy,dist,angle
    __shared__ float2 sf1[WPB][P];                // teammate,keeper

    const int tid  = threadIdx.x;
    const int lane = tid & 31;
    const int wip  = tid >> 5;

    {   // stage W2 into shared once per block
        const float4* W2v  = (const float4*)W2;
        float4*       sW2v = (float4*)sW2;
        #pragma unroll
        for (int i = tid; i < HID * OUTD / 4; i += THREADS) sW2v[i] = W2v[i];
    }

    // W1 columns (lane, lane+32) in registers
    float w1a[INF_], w1b[INF_];
    #pragma unroll
    for (int i = 0; i < INF_; i++) {
        w1a[i] = W1[i * HID + lane];
        w1b[i] = W1[i * HID + lane + 32];
    }
    const float b1a = b1[lane];
    const float b1b = b1[lane + 32];
    float bv[4];
    {   const float4 t = ((const float4*)b2)[lane];
        bv[0] = t.x; bv[1] = t.y; bv[2] = t.z; bv[3] = t.w; }

    __syncthreads();

    const int w = blockIdx.x * WPB + wip;   // global warp id

    // Bresenham-balanced chunks: BASEK base + possibly 1 tail, tail spread evenly.
    const int fw    = (w * 34) / 111;
    const int fw1   = ((w + 1) * 34) / 111;
    const int nmine = BASEK + (fw1 - fw);

    for (int k = 0; k < nmine; k++) {
        const int chunk = (k < BASEK) ? (w + k * NWARPS) : (BASE_CHUNKS + fw);
        const int b0 = chunk * S;
        unsigned gmask = 0;   // bit s = set s non-empty (warp-uniform)

        // ---- per set: load, features, stage 1 (masked sum of relu(f@W1+b1)) ----
        #pragma unroll 1
        for (int s = 0; s < S; s++) {
            const int bset = b0 + s;
            int valid = 0;
            if (lane < P) {
                const int idx = bset * P + lane;
                valid = (mask[idx] != 0);
                if (valid) {
                    const float2 a  = ((const float2*)actor_locs)[bset];
                    const float2 pl = ((const float2*)player_locs)[idx];
                    const float2 fl = ((const float2*)flags)[idx];
                    const float dx = pl.x - a.x;
                    const float dy = pl.y - a.y;
                    const float d2 = fmaf(dx, dx, dy * dy);
                    const float dist = (d2 > 0.f) ? d2 * rsqrtf(d2) : 0.f;
                    const float ang  = fast_atan2(dy, dx);
                    sf0[wip][lane] = make_float4(dx, dy, dist, ang);
                    sf1[wip][lane] = fl;
                }
            }
            unsigned bal = __ballot_sync(0xffffffffu, valid);
            __syncwarp();
            const int cnt = __popc(bal);

            float ha = 0.f, hb = 0.f;
            while (bal) {
                const int p = __ffs(bal) - 1;
                bal &= bal - 1;                       // warp-uniform
                const float4 f0 = sf0[wip][p];        // broadcast LDS.128
                const float2 f1 = sf1[wip][p];        // broadcast LDS.64
                float va = b1a, vb = b1b;
                va = fmaf(f0.x, w1a[0], va);  vb = fmaf(f0.x, w1b[0], vb);
                va = fmaf(f0.y, w1a[1], va);  vb = fmaf(f0.y, w1b[1], vb);
                va = fmaf(f0.z, w1a[2], va);  vb = fmaf(f0.z, w1b[2], vb);
                va = fmaf(f0.w, w1a[3], va);  vb = fmaf(f0.w, w1b[3], vb);
                va = fmaf(f1.x, w1a[4], va);  vb = fmaf(f1.x, w1b[4], vb);
                va = fmaf(f1.y, w1a[5], va);  vb = fmaf(f1.y, w1b[5], vb);
                ha += fmaxf(va, 0.f);
                hb += fmaxf(vb, 0.f);
            }

            const float rc = (cnt > 0) ? __fdividef(1.0f, (float)cnt) : 0.0f;
            gmask |= (cnt > 0) ? (1u << s) : 0u;
            shh[wip][lane     ][s] = ha * rc;
            shh[wip][lane + 32][s] = hb * rc;
            __syncwarp();   // sf0/sf1 reused next set; shh read in stage 2
        }

        // ---- stage 2: out[s] = h[s] @ W2 + gate[s]*b2, 8 sets at a time ----
        // set-pairs p = (0,1),(2,3),(4,5),(6,7); c = output quad component
        unsigned long long acc[4][4];
        #pragma unroll
        for (int p = 0; p < 4; p++) {
            const float g0 = (gmask >> (2 * p))     & 1u ? 1.f : 0.f;
            const float g1 = (gmask >> (2 * p + 1)) & 1u ? 1.f : 0.f;
            #pragma unroll
            for (int c = 0; c < 4; c++)
                acc[p][c] = pack2(bv[c] * g0, bv[c] * g1);
        }

        const float4* w2r = (const float4*)sW2;
        #pragma unroll
        for (int j = 0; j < HID; j++) {
            const float4 wv = w2r[j * (OUTD / 4) + lane];   // per-lane LDS.128
            // h_j for 8 sets: 32B row, two broadcast LDS.128, pairs pre-packed
            const ulonglong2* hp = (const ulonglong2*)&shh[wip][j][0];
            const ulonglong2 hA = hp[0];   // (s0,s1),(s2,s3)
            const ulonglong2 hB = hp[1];   // (s4,s5),(s6,s7)
            const unsigned long long wd0 = pack2(wv.x, wv.x);
            const unsigned long long wd1 = pack2(wv.y, wv.y);
            const unsigned long long wd2 = pack2(wv.z, wv.z);
            const unsigned long long wd3 = pack2(wv.w, wv.w);
            acc[0][0] = fma2(hA.x, wd0, acc[0][0]);
            acc[0][1] = fma2(hA.x, wd1, acc[0][1]);
            acc[0][2] = fma2(hA.x, wd2, acc[0][2]);
            acc[0][3] = fma2(hA.x, wd3, acc[0][3]);
            acc[1][0] = fma2(hA.y, wd0, acc[1][0]);
            acc[1][1] = fma2(hA.y, wd1, acc[1][1]);
            acc[1][2] = fma2(hA.y, wd2, acc[1][2]);
            acc[1][3] = fma2(hA.y, wd3, acc[1][3]);
            acc[2][0] = fma2(hB.x, wd0, acc[2][0]);
            acc[2][1] = fma2(hB.x, wd1, acc[2][1]);
            acc[2][2] = fma2(hB.x, wd2, acc[2][2]);
            acc[2][3] = fma2(hB.x, wd3, acc[2][3]);
            acc[3][0] = fma2(hB.y, wd0, acc[3][0]);
            acc[3][1] = fma2(hB.y, wd1, acc[3][1]);
            acc[3][2] = fma2(hB.y, wd2, acc[3][2]);
            acc[3][3] = fma2(hB.y, wd3, acc[3][3]);
        }

        // ---- unpack and store: one STG.128 per set ----
        float4* ov = (float4*)out;
        #pragma unroll
        for (int p = 0; p < 4; p++) {
            float4 oa, ob;
            unpack2(acc[p][0], oa.x, ob.x);
            unpack2(acc[p][1], oa.y, ob.y);
            unpack2(acc[p][2], oa.z, ob.z);
            unpack2(acc[p][3], oa.w, ob.w);
            ov[(b0 + 2 * p)     * (OUTD / 4) + lane] = oa;
            ov[(b0 + 2 * p + 1) * (OUTD / 4) + lane] = ob;
        }
    }
}

extern "C" void kernel_launch(void* const* d_in, const int* in_sizes, int n_in,
                              void* d_out, int out_size)
{
    const float* player_locs = (const float*)d_in[0];
    const float* actor_locs  = (const float*)d_in[1];
    const float* flags       = (const float*)d_in[2];
    const int*   mask        = (const int*)  d_in[3];
    const float* W1          = (const float*)d_in[4];
    const float* b1          = (const float*)d_in[5];
    const float* W2          = (const float*)d_in[6];
    const float* b2          = (const float*)d_in[7];
    float*       out         = (float*)d_out;

    set_encoder_kernel<<<GRID, THREADS>>>(player_locs, actor_locs, flags, mask,
                                          W1, b1, W2, b2, out);
}